// round 3
// baseline (speedup 1.0000x reference)
#include <cuda_runtime.h>
#include <math.h>

#define Bb   1024
#define Ll   256
#define Mm   256
#define Hh   64
#define Vv   64
#define G3   192
#define LH   32
#define NB   8      // batches per block
#define NBLK 128
#define NT   256

// ---------------- device scratch (no allocations allowed) ----------------
__device__ float        d_E2[Vv * G3];       // embed @ Wx^T + b_ih   (64 x 192)
__device__ float        d_A2[Hh * Hh];       // (k_w^T q_w) / sqrt(H)
__device__ float        d_a0[Hh];            // (k_w^T q_b) / sqrt(H)
__device__ float        d_gpart[Ll * NBLK];  // per-step per-block prob partial sums
__device__ unsigned int d_gcnt[Ll];          // per-step arrival counters

__device__ __forceinline__ float sigf(float x)  { return 1.f / (1.f + __expf(-x)); }
__device__ __forceinline__ float tanhfast(float x) { return 2.f / (1.f + __expf(-2.f * x)) - 1.f; }

// ---------------- prep: tables + reset sync slots ----------------
__global__ void prep_kernel(const float* __restrict__ embed,
                            const float* __restrict__ gwih,
                            const float* __restrict__ gbih,
                            const float* __restrict__ kw,
                            const float* __restrict__ qw,
                            const float* __restrict__ qb) {
    const int idx = blockIdx.x * blockDim.x + threadIdx.x;
    const int stride = gridDim.x * blockDim.x;
    for (int i = idx; i < Vv * G3; i += stride) {
        const int v = i / G3, k = i % G3;
        float s = gbih[k];
        const float* e = embed + v * Hh;
        const float* w = gwih + k * (2 * Hh);       // first H columns multiply x
        #pragma unroll 8
        for (int j = 0; j < Hh; j++) s = fmaf(e[j], w[j], s);
        d_E2[i] = s;
    }
    for (int i = idx; i < Hh * Hh; i += stride) {
        const int a = i >> 6, l = i & 63;           // A2[a][l]
        float s = 0.f;
        for (int t = 0; t < Hh; t++) s = fmaf(kw[t * Hh + a], qw[t * Hh + l], s);
        d_A2[i] = s * 0.125f;                        // 1/sqrt(64)
    }
    for (int i = idx; i < Hh; i += stride) {
        float s = 0.f;
        for (int t = 0; t < Hh; t++) s = fmaf(kw[t * Hh + i], qb[t], s);
        d_a0[i] = s * 0.125f;
    }
    for (int i = idx; i < Ll; i += stride) d_gcnt[i] = 0u;
}

// ---------------- SMEM layout (float offsets) ----------------
#define OFF_GWHH 0        /* 64x192 transposed gru_whh          */
#define OFF_WR   12288    /* 64x192 transposed gru_wih[:,64:]   */
#define OFF_LWIH 24576    /* 64x128 transposed lstm_wih         */
#define OFF_LWHH 32768    /* 32x128 transposed lstm_whh         */
#define OFF_A2   36864    /* 64x64  A2 transposed [l][a]        */
#define OFF_VW   40960    /* 64x64  v_w transposed [j][k]       */
#define OFF_GBHH 45056    /* 192 */
#define OFF_LB2  45248    /* 128  lbih+lbhh */
#define OFF_A0   45376    /* 64  */
#define OFF_VB   45440    /* 64  */
#define OFF_TW   45504    /* 32  */
#define OFF_SC   45536    /* [0]=trig_b */
#define OFF_HP   45552    /* 8x64  h state */
#define OFF_XW   46064    /* 4x8x128 lstm xW ring */
#define OFF_GH   50160    /* 8x192 */
#define OFF_GI   51696    /* 8x192 */
#define OFF_GATE 53232    /* 8x128 */
#define OFF_HH   54256    /* 8x32 */
#define OFF_CC   54512    /* 8x32 */
#define OFF_Q2   54768    /* 8x64 */
#define OFF_WS   55280    /* 8x64 */
#define OFF_RET  55792    /* 8x64 */
#define OFF_PROB 56304    /* 8 */
#define OFF_RED  56312    /* 128 */
#define OFF_FLAG 56440    /* 4 */
#define OFF_TOK  56444    /* 8 ints */
#define SMEM_FLOATS 56464
#define SMEM_BYTES  (SMEM_FLOATS * 4)

__global__ void __launch_bounds__(NT, 1) model_kernel(
    const int*   __restrict__ seq,
    const float* __restrict__ memory,
    const float* __restrict__ gwih,
    const float* __restrict__ gwhh,
    const float* __restrict__ gbhh,
    const float* __restrict__ vw,
    const float* __restrict__ vb,
    const float* __restrict__ lwih,
    const float* __restrict__ lwhh,
    const float* __restrict__ lbih,
    const float* __restrict__ lbhh,
    const float* __restrict__ trigw,
    const float* __restrict__ trigb,
    const float* __restrict__ headw,
    const float* __restrict__ headb,
    float* __restrict__ out,
    int out_size)
{
    extern __shared__ float sm[];
    const int tid = threadIdx.x;
    const int b0  = blockIdx.x * NB;
    int* s_tok = (int*)(sm + OFF_TOK);

    // ---- load + transpose weights into SMEM ----
    for (int i = tid; i < 12288; i += NT)            // gwhh^T [j][k]
        sm[OFF_GWHH + i] = gwhh[(i % 192) * 64 + (i / 192)];
    for (int i = tid; i < 12288; i += NT)            // Wr^T [j][k] (retrieved half of gru_wih)
        sm[OFF_WR + i] = gwih[(i % 192) * 128 + 64 + (i / 192)];
    for (int i = tid; i < 8192; i += NT)             // lstm_wih^T [j][k]
        sm[OFF_LWIH + i] = lwih[(i % 128) * 64 + (i / 128)];
    for (int i = tid; i < 4096; i += NT)             // lstm_whh^T [j][k]
        sm[OFF_LWHH + i] = lwhh[(i % 128) * 32 + (i / 128)];
    for (int i = tid; i < 4096; i += NT)             // A2^T [l][a]
        sm[OFF_A2 + i] = d_A2[(i % 64) * 64 + (i / 64)];
    for (int i = tid; i < 4096; i += NT)             // v_w^T [j][k]
        sm[OFF_VW + i] = vw[(i % 64) * 64 + (i / 64)];
    for (int i = tid; i < 192; i += NT) sm[OFF_GBHH + i] = gbhh[i];
    for (int i = tid; i < 128; i += NT) sm[OFF_LB2 + i] = lbih[i] + lbhh[i];
    for (int i = tid; i < 64; i += NT)  { sm[OFF_A0 + i] = d_a0[i]; sm[OFF_VB + i] = vb[i]; }
    for (int i = tid; i < 32; i += NT)  sm[OFF_TW + i] = trigw[i];
    if (tid == 0) sm[OFF_SC] = trigb[0];
    for (int i = tid; i < NB * Hh; i += NT) sm[OFF_HP + i] = 0.f;   // h = 0
    __syncthreads();

    int read_prev = 0;
    int nreads = 0;

    for (int t = 0; t < Ll; t++) {
        // ---------- phase A: tokens + gh = h@gwhh^T + bhh  (+ ret@Wr^T if read_prev) ----------
        if (tid < NB) s_tok[tid] = seq[(b0 + tid) * Ll + t];
        if (tid < 192) {
            const int k = tid;
            float acc[NB];
            const float bias = sm[OFF_GBHH + k];
            #pragma unroll
            for (int b = 0; b < NB; b++) acc[b] = bias;
            #pragma unroll 4
            for (int j = 0; j < 64; j += 4) {
                const float w0 = sm[OFF_GWHH + (j + 0) * 192 + k];
                const float w1 = sm[OFF_GWHH + (j + 1) * 192 + k];
                const float w2 = sm[OFF_GWHH + (j + 2) * 192 + k];
                const float w3 = sm[OFF_GWHH + (j + 3) * 192 + k];
                #pragma unroll
                for (int b = 0; b < NB; b++) {
                    const float4 h4 = *(const float4*)&sm[OFF_HP + b * 64 + j];
                    acc[b] = fmaf(w0, h4.x, acc[b]);
                    acc[b] = fmaf(w1, h4.y, acc[b]);
                    acc[b] = fmaf(w2, h4.z, acc[b]);
                    acc[b] = fmaf(w3, h4.w, acc[b]);
                }
            }
            #pragma unroll
            for (int b = 0; b < NB; b++) sm[OFF_GH + b * 192 + k] = acc[b];

            if (read_prev) {
                float ac2[NB];
                #pragma unroll
                for (int b = 0; b < NB; b++) ac2[b] = 0.f;
                #pragma unroll 4
                for (int j = 0; j < 64; j += 4) {
                    const float w0 = sm[OFF_WR + (j + 0) * 192 + k];
                    const float w1 = sm[OFF_WR + (j + 1) * 192 + k];
                    const float w2 = sm[OFF_WR + (j + 2) * 192 + k];
                    const float w3 = sm[OFF_WR + (j + 3) * 192 + k];
                    #pragma unroll
                    for (int b = 0; b < NB; b++) {
                        const float4 r4 = *(const float4*)&sm[OFF_RET + b * 64 + j];
                        ac2[b] = fmaf(w0, r4.x, ac2[b]);
                        ac2[b] = fmaf(w1, r4.y, ac2[b]);
                        ac2[b] = fmaf(w2, r4.z, ac2[b]);
                        ac2[b] = fmaf(w3, r4.w, ac2[b]);
                    }
                }
                #pragma unroll
                for (int b = 0; b < NB; b++) sm[OFF_GI + b * 192 + k] = ac2[b];
            }
        }
        __syncthreads();

        // ---------- phase B: GRU combine -> new h ----------
        #pragma unroll
        for (int it = tid; it < NB * Hh; it += NT) {
            const int b = it >> 6, k = it & 63;
            const int tok = s_tok[b];
            float gi_r = __ldg(&d_E2[tok * 192 + k]);
            float gi_z = __ldg(&d_E2[tok * 192 + 64 + k]);
            float gi_n = __ldg(&d_E2[tok * 192 + 128 + k]);
            if (read_prev) {
                gi_r += sm[OFF_GI + b * 192 + k];
                gi_z += sm[OFF_GI + b * 192 + 64 + k];
                gi_n += sm[OFF_GI + b * 192 + 128 + k];
            }
            const float gh_r = sm[OFF_GH + b * 192 + k];
            const float gh_z = sm[OFF_GH + b * 192 + 64 + k];
            const float gh_n = sm[OFF_GH + b * 192 + 128 + k];
            const float r = sigf(gi_r + gh_r);
            const float z = sigf(gi_z + gh_z);
            const float n = tanhfast(fmaf(r, gh_n, gi_n));
            const float h = sm[OFF_HP + b * 64 + k];
            sm[OFF_HP + b * 64 + k] = n + z * (h - n);   // (1-z)n + z h
        }
        __syncthreads();

        // ---------- phase C: trigger input projection xW for new h -> ring slot ----------
        if (tid < 128) {
            const int k = tid;
            float acc[NB];
            #pragma unroll
            for (int b = 0; b < NB; b++) acc[b] = 0.f;
            #pragma unroll 4
            for (int j = 0; j < 64; j += 4) {
                const float w0 = sm[OFF_LWIH + (j + 0) * 128 + k];
                const float w1 = sm[OFF_LWIH + (j + 1) * 128 + k];
                const float w2 = sm[OFF_LWIH + (j + 2) * 128 + k];
                const float w3 = sm[OFF_LWIH + (j + 3) * 128 + k];
                #pragma unroll
                for (int b = 0; b < NB; b++) {
                    const float4 h4 = *(const float4*)&sm[OFF_HP + b * 64 + j];
                    acc[b] = fmaf(w0, h4.x, acc[b]);
                    acc[b] = fmaf(w1, h4.y, acc[b]);
                    acc[b] = fmaf(w2, h4.z, acc[b]);
                    acc[b] = fmaf(w3, h4.w, acc[b]);
                }
            }
            #pragma unroll
            for (int b = 0; b < NB; b++)
                sm[OFF_XW + (t & 3) * 1024 + b * 128 + k] = acc[b];
        }

        int do_read = 0;
        if (t >= 3) {
            __syncthreads();
            // ---------- phase D: trigger LSTM over 4 cached hist inputs ----------
            #pragma unroll
            for (int s = 0; s < 4; s++) {
                const int slot = (t + 1 + s) & 3;
                if (tid < 128) {
                    const int k = tid;
                    float acc[NB];
                    #pragma unroll
                    for (int b = 0; b < NB; b++)
                        acc[b] = sm[OFF_XW + slot * 1024 + b * 128 + k] + sm[OFF_LB2 + k];
                    if (s > 0) {
                        #pragma unroll 2
                        for (int j = 0; j < 32; j += 4) {
                            const float w0 = sm[OFF_LWHH + (j + 0) * 128 + k];
                            const float w1 = sm[OFF_LWHH + (j + 1) * 128 + k];
                            const float w2 = sm[OFF_LWHH + (j + 2) * 128 + k];
                            const float w3 = sm[OFF_LWHH + (j + 3) * 128 + k];
                            #pragma unroll
                            for (int b = 0; b < NB; b++) {
                                const float4 h4 = *(const float4*)&sm[OFF_HH + b * 32 + j];
                                acc[b] = fmaf(w0, h4.x, acc[b]);
                                acc[b] = fmaf(w1, h4.y, acc[b]);
                                acc[b] = fmaf(w2, h4.z, acc[b]);
                                acc[b] = fmaf(w3, h4.w, acc[b]);
                            }
                        }
                    }
                    #pragma unroll
                    for (int b = 0; b < NB; b++) sm[OFF_GATE + b * 128 + k] = acc[b];
                }
                __syncthreads();
                {   // gate nonlinearity: 8 batches x 32 units
                    const int b = tid >> 5, k = tid & 31;
                    const float g_i = sm[OFF_GATE + b * 128 + k];
                    const float g_f = sm[OFF_GATE + b * 128 + 32 + k];
                    const float g_g = sm[OFF_GATE + b * 128 + 64 + k];
                    const float g_o = sm[OFF_GATE + b * 128 + 96 + k];
                    float c = sigf(g_i) * tanhfast(g_g);
                    if (s > 0) c = fmaf(sigf(g_f), sm[OFF_CC + b * 32 + k], c);
                    sm[OFF_CC + b * 32 + k] = c;
                    sm[OFF_HH + b * 32 + k] = sigf(g_o) * tanhfast(c);
                }
                __syncthreads();
            }

            // ---------- phase E: prob per batch + deterministic grid mean ----------
            {
                const int w = tid >> 5, ln = tid & 31;
                float v = sm[OFF_HH + w * 32 + ln] * sm[OFF_TW + ln];
                #pragma unroll
                for (int o = 16; o > 0; o >>= 1) v += __shfl_xor_sync(0xffffffffu, v, o);
                if (ln == 0) sm[OFF_PROB + w] = sigf(v + sm[OFF_SC]);
            }
            __syncthreads();
            if (tid == 0) {
                float part = 0.f;
                #pragma unroll
                for (int i = 0; i < NB; i++) part += sm[OFF_PROB + i];
                d_gpart[t * NBLK + blockIdx.x] = part;
                __threadfence();
                atomicAdd(&d_gcnt[t], 1u);
                while (*((volatile unsigned int*)&d_gcnt[t]) < (unsigned)NBLK) { __nanosleep(64); }
                __threadfence();
            }
            __syncthreads();
            if (tid < NBLK) sm[OFF_RED + tid] = __ldcg(&d_gpart[t * NBLK + tid]);
            __syncthreads();
            if (tid == 0) {
                float s0 = 0.f, s1 = 0.f, s2 = 0.f, s3 = 0.f;
                for (int i = 0; i < NBLK; i += 4) {
                    s0 += sm[OFF_RED + i];     s1 += sm[OFF_RED + i + 1];
                    s2 += sm[OFF_RED + i + 2]; s3 += sm[OFF_RED + i + 3];
                }
                const float mean = ((s0 + s1) + (s2 + s3)) * (1.f / 1024.f);
                sm[OFF_FLAG] = (mean > 0.5f) ? 1.f : 0.f;
            }
            __syncthreads();
            do_read = (sm[OFF_FLAG] != 0.f);

            if (do_read) {
                // ---------- phase F: attention ----------
                if (tid < 64) {                       // q2 = A2 h + a0
                    const int k = tid;
                    float acc[NB];
                    #pragma unroll
                    for (int b = 0; b < NB; b++) acc[b] = sm[OFF_A0 + k];
                    #pragma unroll 4
                    for (int j = 0; j < 64; j += 4) {
                        const float w0 = sm[OFF_A2 + (j + 0) * 64 + k];
                        const float w1 = sm[OFF_A2 + (j + 1) * 64 + k];
                        const float w2 = sm[OFF_A2 + (j + 2) * 64 + k];
                        const float w3 = sm[OFF_A2 + (j + 3) * 64 + k];
                        #pragma unroll
                        for (int b = 0; b < NB; b++) {
                            const float4 h4 = *(const float4*)&sm[OFF_HP + b * 64 + j];
                            acc[b] = fmaf(w0, h4.x, acc[b]);
                            acc[b] = fmaf(w1, h4.y, acc[b]);
                            acc[b] = fmaf(w2, h4.z, acc[b]);
                            acc[b] = fmaf(w3, h4.w, acc[b]);
                        }
                    }
                    #pragma unroll
                    for (int b = 0; b < NB; b++) sm[OFF_Q2 + b * 64 + k] = acc[b];
                }
                __syncthreads();
                {   // one warp per batch: streaming online softmax over memory
                    const int w = tid >> 5, ln = tid & 31;
                    const float* mb = memory + (size_t)(b0 + w) * (Mm * Hh);
                    const float q0 = sm[OFF_Q2 + w * 64 + 2 * ln];
                    const float q1 = sm[OFF_Q2 + w * 64 + 2 * ln + 1];
                    float mx = -3.0e38f, dn = 0.f, ra = 0.f, rb = 0.f;
                    #pragma unroll 4
                    for (int m = 0; m < Mm; m++) {
                        const float2 mm = *(const float2*)(mb + m * 64 + 2 * ln);
                        float p = q0 * mm.x + q1 * mm.y;
                        #pragma unroll
                        for (int o = 16; o > 0; o >>= 1) p += __shfl_xor_sync(0xffffffffu, p, o);
                        const float sc = p * 0.125f;
                        const float nm = fmaxf(mx, sc);
                        const float f  = __expf(mx - nm);
                        const float e  = __expf(sc - nm);
                        dn = fmaf(dn, f, e);
                        ra = fmaf(ra, f, e * mm.x);
                        rb = fmaf(rb, f, e * mm.y);
                        mx = nm;
                    }
                    const float inv = 1.f / dn;
                    sm[OFF_WS + w * 64 + 2 * ln]     = ra * inv;
                    sm[OFF_WS + w * 64 + 2 * ln + 1] = rb * inv;
                }
                __syncthreads();
                if (tid < 64) {                       // retrieved = v_w ws + v_b
                    const int k = tid;
                    float acc[NB];
                    #pragma unroll
                    for (int b = 0; b < NB; b++) acc[b] = sm[OFF_VB + k];
                    #pragma unroll 4
                    for (int j = 0; j < 64; j += 4) {
                        const float w0 = sm[OFF_VW + (j + 0) * 64 + k];
                        const float w1 = sm[OFF_VW + (j + 1) * 64 + k];
                        const float w2 = sm[OFF_VW + (j + 2) * 64 + k];
                        const float w3 = sm[OFF_VW + (j + 3) * 64 + k];
                        #pragma unroll
                        for (int b = 0; b < NB; b++) {
                            const float4 s4 = *(const float4*)&sm[OFF_WS + b * 64 + j];
                            acc[b] = fmaf(w0, s4.x, acc[b]);
                            acc[b] = fmaf(w1, s4.y, acc[b]);
                            acc[b] = fmaf(w2, s4.z, acc[b]);
                            acc[b] = fmaf(w3, s4.w, acc[b]);
                        }
                    }
                    #pragma unroll
                    for (int b = 0; b < NB; b++) sm[OFF_RET + b * 64 + k] = acc[b];
                }
                nreads++;
            }
            read_prev = do_read;
        } else {
            read_prev = 0;
        }
        __syncthreads();
    }

    // ---------- epilogue: logits = h @ head_w^T + head_b ----------
    if (tid < 64) {
        const int k = tid;
        float acc[NB];
        const float hb = __ldg(&headb[k]);
        #pragma unroll
        for (int b = 0; b < NB; b++) acc[b] = hb;
        #pragma unroll 4
        for (int j = 0; j < 64; j += 4) {
            const float4 w4 = __ldg((const float4*)(headw + k * 64 + j));
            #pragma unroll
            for (int b = 0; b < NB; b++) {
                const float4 h4 = *(const float4*)&sm[OFF_HP + b * 64 + j];
                acc[b] = fmaf(w4.x, h4.x, acc[b]);
                acc[b] = fmaf(w4.y, h4.y, acc[b]);
                acc[b] = fmaf(w4.z, h4.z, acc[b]);
                acc[b] = fmaf(w4.w, h4.w, acc[b]);
            }
        }
        #pragma unroll
        for (int b = 0; b < NB; b++) out[(size_t)(b0 + b) * Vv + k] = acc[b];
    }
    if (blockIdx.x == 0 && tid == 0) {
        const float rr = (float)nreads * (1.f / (float)Ll);
        for (int i = Bb * Vv; i < out_size; i++) out[i] = rr;
    }
}

extern "C" void kernel_launch(void* const* d_in, const int* in_sizes, int n_in,
                              void* d_out, int out_size) {
    const int*   seq    = (const int*)  d_in[0];
    const float* memory = (const float*)d_in[1];
    const float* embed  = (const float*)d_in[2];
    const float* gwih   = (const float*)d_in[3];
    const float* gwhh   = (const float*)d_in[4];
    const float* gbih   = (const float*)d_in[5];
    const float* gbhh   = (const float*)d_in[6];
    const float* qw     = (const float*)d_in[7];
    const float* qb     = (const float*)d_in[8];
    const float* kw     = (const float*)d_in[9];
    /* k_b (d_in[10]) cancels in softmax — unused */
    const float* vw     = (const float*)d_in[11];
    const float* vb     = (const float*)d_in[12];
    const float* lwih   = (const float*)d_in[13];
    const float* lwhh   = (const float*)d_in[14];
    const float* lbih   = (const float*)d_in[15];
    const float* lbhh   = (const float*)d_in[16];
    const float* trigw  = (const float*)d_in[17];
    const float* trigb  = (const float*)d_in[18];
    const float* headw  = (const float*)d_in[19];
    const float* headb  = (const float*)d_in[20];
    float* out = (float*)d_out;

    cudaFuncSetAttribute(model_kernel,
                         cudaFuncAttributeMaxDynamicSharedMemorySize, SMEM_BYTES);

    prep_kernel<<<64, 256>>>(embed, gwih, gbih, kw, qw, qb);
    model_kernel<<<NBLK, NT, SMEM_BYTES>>>(seq, memory, gwih, gwhh, gbhh,
                                           vw, vb, lwih, lwhh, lbih, lbhh,
                                           trigw, trigb, headw, headb,
                                           out, out_size);
}